// round 16
// baseline (speedup 1.0000x reference)
#include <cuda_runtime.h>
#include <cstdint>
#include <math.h>

// Problem dims
#define Bn  256
#define Tn  512
#define Fn  128
#define CUn 512
#define DUn 512
#define KX  640
#define NG  2048
#define Rn  (Bn*Tn)

// Producer v3 tiling: CTA tile 256 x 128, warp tile 32x64, double-buffered
#define PBK  32
#define PAST 36          // A stride (36%32==4 conflict-free)
#define PBST 136         // B stride (136%32==8 conflict-free)
#define PA_OFF 0                         // 2 x 256*36  = 18432 floats
#define PB_OFF (2*256*PAST)              // 2 x 32*136  =  8704 floats
#define ZTILES_T 16                      // Zpre tiles per t (2048/128)
#define TOTAL_TILES (Tn * ZTILES_T)

// k_out tiling
#define BM 128
#define BN 64
#define BK 32
#define ASTR 36
#define BSTR 72

// Consumer config (round-13/14, verified): 64 CTAs = 2 row-groups x 32 col-groups
#define NREC   64
#define NCTA_ALL 148
#define NRGC   32
#define UST    72
#define BKC    64
#define H64S   68
#define NKT    (DUn/BKC)

// Scratch
__device__ float g_Zpre[(size_t)Rn * NG];
__device__ float g_H[(size_t)Rn * DUn];
__device__ float g_h0r[Bn * DUn];
__device__ float g_Wr[(size_t)KX * NG];      // tf32-rounded W
__device__ float g_Xr[(size_t)Rn * KX];      // tf32-rounded [teacher_{t-1} | cond_t]
__device__ unsigned g_rbar[2];
__device__ unsigned g_work;
__device__ unsigned g_zdone[Tn];

__device__ __forceinline__ uint32_t f2tf(float x){
    uint32_t r; asm("cvt.rna.tf32.f32 %0, %1;" : "=r"(r) : "f"(x)); return r;
}
__device__ __forceinline__ float tf2f(uint32_t u){ return __uint_as_float(u); }
__device__ __forceinline__ void st4_tf(float* dst, float4 v){
    dst[0]=tf2f(f2tf(v.x)); dst[1]=tf2f(f2tf(v.y));
    dst[2]=tf2f(f2tf(v.z)); dst[3]=tf2f(f2tf(v.w));
}
__device__ __forceinline__ void mma_tf32(float d[4],
        uint32_t a0, uint32_t a1, uint32_t a2, uint32_t a3,
        uint32_t b0, uint32_t b1){
    asm volatile(
        "mma.sync.aligned.m16n8k8.row.col.f32.tf32.tf32.f32 "
        "{%0,%1,%2,%3}, {%4,%5,%6,%7}, {%8,%9}, {%0,%1,%2,%3};\n"
        : "+f"(d[0]), "+f"(d[1]), "+f"(d[2]), "+f"(d[3])
        : "r"(a0), "r"(a1), "r"(a2), "r"(a3), "r"(b0), "r"(b1));
}
__device__ __forceinline__ float sigm(float x){ return 1.f/(1.f + __expf(-x)); }

__device__ __forceinline__ unsigned ld_acq(const unsigned* p){
    unsigned v;
    asm volatile("ld.global.acquire.gpu.b32 %0, [%1];" : "=r"(v) : "l"(p));
    return v;
}
__device__ __forceinline__ void red_rel_add(unsigned* p, unsigned v){
    asm volatile("red.release.gpu.global.add.u32 [%0], %1;" :: "l"(p), "r"(v) : "memory");
}
__device__ __forceinline__ void nsleep(unsigned ns){
    asm volatile("nanosleep.u32 %0;" :: "r"(ns));
}

#define CPA16(dst_u32, src_ptr) \
    asm volatile("cp.async.ca.shared.global [%0], [%1], 16;\n" \
                 :: "r"(dst_u32), "l"(src_ptr))
#define CPA_COMMIT() asm volatile("cp.async.commit_group;\n" ::: "memory")

// Consumer SMEM floats: Us 512*72 = 36864 | A ring 2 x 128*68 = 17408
#define US_OFF   0
#define AS_OFF   (512*UST)
#define SM_FLOATS (AS_OFF + 2*128*H64S)      // 54272 floats = 217088 B
// (producer uses a 27136-float prefix of the same dynamic SMEM)

// ===========================================================================
// Consumer (verified bit-identical): CTA (rg,cg) = rows rg*128..+128,
// units cg*16..+16; 16 warps = 8M x 2N, warp 16x32, serial K, c in regs.
// ===========================================================================
__device__ void consumer_role(const float* __restrict__ U,
                              const float* __restrict__ c0,
                              float* __restrict__ out,
                              float* sm){
    float* Us = sm + US_OFF;
    float* As = sm + AS_OFF;

    const int tid = threadIdx.x, lane = tid & 31, wid = tid >> 5;
    const int qr = lane >> 2, qc = lane & 3;
    const int wm = wid >> 1, wn = wid & 1;
    const int rg = blockIdx.x >> 5, cg = blockIdx.x & 31;
    const int mrow = wm * 16;
    const int j0 = cg * 16;
    const int ju = j0 + wn*8 + qc*2;

    for (int i = tid; i < 512*64; i += 512){
        int k = i >> 6, c = i & 63;
        int q = c >> 4, j = c & 15;
        Us[k*UST + c] = tf2f(f2tf(U[(size_t)k*NG + q*DUn + j0 + j]));
    }
    float creg[2][2];
    {
        int grow = rg*128 + mrow + qr;
        float2 cA = *reinterpret_cast<const float2*>(c0 + (size_t)grow*DUn + ju);
        float2 cB = *reinterpret_cast<const float2*>(c0 + (size_t)(grow+8)*DUn + ju);
        creg[0][0]=cA.x; creg[0][1]=cA.y; creg[1][0]=cB.x; creg[1][1]=cB.y;
    }
    __syncthreads();

    const uint32_t as_u32 = (uint32_t)__cvta_generic_to_shared(As);

    for (int t = 0; t < Tn; t++){
        const float* hsrc = ((t == 0) ? g_h0r : (g_H + (size_t)(t-1)*Bn*DUn))
                            + (size_t)rg*128*DUn;

        if (tid == 0){
            unsigned s = 0;
            while (ld_acq(&g_zdone[t]) < (unsigned)ZTILES_T){
                nsleep(s); if (s < 256) s += 64;
            }
        }
        __syncthreads();

        float2 zp[2][4];
        {
            const float* zr0 = g_Zpre + ((size_t)t*Bn + rg*128 + mrow + qr)*NG + ju;
            const float* zr1 = zr0 + 8*NG;
            #pragma unroll
            for (int g = 0; g < 4; g++){
                zp[0][g] = *reinterpret_cast<const float2*>(zr0 + g*DUn);
                zp[1][g] = *reinterpret_cast<const float2*>(zr1 + g*DUn);
            }
        }

        #pragma unroll
        for (int i = 0; i < 4; i++){
            int s = tid + i*512;
            int r = s >> 4, c4 = (s & 15) * 4;
            CPA16(as_u32 + (uint32_t)(r*H64S + c4)*4u, hsrc + (size_t)r*DUn + c4);
        }
        CPA_COMMIT();

        float acc[4][4];
        #pragma unroll
        for (int nt=0;nt<4;nt++)
            #pragma unroll
            for (int i=0;i<4;i++) acc[nt][i]=0.f;

        for (int kt = 0; kt < NKT; kt++){
            asm volatile("cp.async.wait_group 0;\n" ::: "memory");
            __syncthreads();
            if (kt + 1 < NKT){
                uint32_t bb = as_u32 + (uint32_t)(((kt+1)&1)*128*H64S)*4u;
                int k0n = (kt+1)*BKC;
                #pragma unroll
                for (int i = 0; i < 4; i++){
                    int s = tid + i*512;
                    int r = s >> 4, c4 = (s & 15) * 4;
                    CPA16(bb + (uint32_t)(r*H64S + c4)*4u,
                          hsrc + (size_t)r*DUn + k0n + c4);
                }
                CPA_COMMIT();
            }
            {
                const float* Asb = As + (kt & 1)*128*H64S;
                const int k0 = kt * BKC;
                #pragma unroll
                for (int k8 = 0; k8 < BKC; k8 += 8){
                    const float* ap = Asb + (mrow + qr) * H64S + k8 + qc;
                    uint32_t a0 = __float_as_uint(ap[0]);
                    uint32_t a1 = __float_as_uint(ap[8*H64S]);
                    uint32_t a2 = __float_as_uint(ap[4]);
                    uint32_t a3 = __float_as_uint(ap[8*H64S + 4]);
                    #pragma unroll
                    for (int q = 0; q < 4; q++){
                        const float* bp = Us + (k0 + k8 + qc)*UST + q*16 + wn*8 + qr;
                        uint32_t b0 = __float_as_uint(bp[0]);
                        uint32_t b1 = __float_as_uint(bp[4*UST]);
                        mma_tf32(acc[q], a0, a1, a2, a3, b0, b1);
                    }
                }
            }
        }

        {
            float hv[2][2], cvv[2][2];
            #pragma unroll
            for (int rr = 0; rr < 2; rr++){
                #pragma unroll
                for (int uu = 0; uu < 2; uu++){
                    int k = rr*2 + uu;
                    float zi = acc[0][k] + (uu ? zp[rr][0].y : zp[rr][0].x);
                    float zf = acc[1][k] + (uu ? zp[rr][1].y : zp[rr][1].x);
                    float zg = acc[2][k] + (uu ? zp[rr][2].y : zp[rr][2].x);
                    float zo = acc[3][k] + (uu ? zp[rr][3].y : zp[rr][3].x);
                    float si = sigm(zi), sf = sigm(zf), so = sigm(zo);
                    float tg = tanhf(zg);
                    float cn = sf*creg[rr][uu] + si*tg;
                    float hn = so * tanhf(cn);
                    creg[rr][uu] = cn;
                    cvv[rr][uu] = cn;
                    hv[rr][uu] = tf2f(f2tf(hn));
                }
            }
            #pragma unroll
            for (int rr = 0; rr < 2; rr++){
                int grow = rg*128 + mrow + qr + rr*8;
                *reinterpret_cast<float2*>(g_H + ((size_t)t*Bn + grow)*DUn + ju)
                    = make_float2(hv[rr][0], hv[rr][1]);
                if (t == Tn - 1){
                    *reinterpret_cast<float2*>(out + (size_t)Bn*Tn*Fn
                                               + (size_t)grow*DUn + ju)
                        = make_float2(hv[rr][0], hv[rr][1]);
                    *reinterpret_cast<float2*>(out + (size_t)Bn*Tn*Fn + Bn*DUn
                                               + (size_t)grow*DUn + ju)
                        = make_float2(cvv[rr][0], cvv[rr][1]);
                }
            }
        }
        __syncthreads();

        if (t < Tn - 1){
            if (tid == 0){
                red_rel_add(&g_rbar[rg], 1u);
                unsigned target = (unsigned)NRGC * (unsigned)(t + 1);
                unsigned s = 0;
                while (ld_acq(&g_rbar[rg]) < target){ nsleep(s); if (s < 128) s += 32; }
            }
            __syncthreads();
        }
    }
}

// ===========================================================================
// Producer v3: Zpre tiles 256x128, t-major queue; warp tile 32x64
// (2 m16 x 8 n8 = 16 independent mmas per k8, 1.5 LDS/mma). cp.async
// double-buffered, one sync per k-tile. Serial K -> Zpre bit-identical.
// ===========================================================================
__device__ void producer_role(const float* __restrict__ bias, float* sm){
    float* Abuf = sm + PA_OFF;
    float* Bbuf = sm + PB_OFF;
    __shared__ unsigned s_tile;
    const int tid = threadIdx.x, lane = tid & 31, wid = tid >> 5;
    const int wm = wid >> 1, wn = wid & 1;   // 8 in M x 2 in N
    const int qr = lane >> 2, qc = lane & 3;

    const uint32_t a_u32 = (uint32_t)__cvta_generic_to_shared(Abuf);
    const uint32_t b_u32 = (uint32_t)__cvta_generic_to_shared(Bbuf);

    for (;;){
        if (tid == 0) s_tile = atomicAdd(&g_work, 1u);
        __syncthreads();
        unsigned n = s_tile;
        if (n >= (unsigned)TOTAL_TILES) break;
        __syncthreads();
        const int t  = (int)(n >> 4);
        const int n0 = (int)(n & 15) * 128;
        const float* xrow = g_Xr + (size_t)t*Bn*KX;

        float acc[2][8][4];
        #pragma unroll
        for (int mt=0;mt<2;mt++)
            #pragma unroll
            for (int nt=0;nt<8;nt++)
                #pragma unroll
                for (int i=0;i<4;i++) acc[mt][nt][i]=0.f;

        // prologue: k-tile 0 into buf 0
        #pragma unroll
        for (int i = 0; i < 4; i++){
            int s = tid + i*512;
            int r = s >> 3, c4 = (s & 7) * 4;
            CPA16(a_u32 + (uint32_t)(r*PAST + c4)*4u, xrow + (size_t)r*KX + c4);
        }
        #pragma unroll
        for (int i = 0; i < 2; i++){
            int s = tid + i*512;
            int kr = s >> 5, c4 = (s & 31) * 4;
            CPA16(b_u32 + (uint32_t)(kr*PBST + c4)*4u,
                  g_Wr + (size_t)kr*NG + n0 + c4);
        }
        CPA_COMMIT();

        for (int kt = 0; kt < KX/PBK; kt++){
            asm volatile("cp.async.wait_group 0;\n" ::: "memory");
            __syncthreads();             // k-tile kt ready AND other buf free
            if (kt + 1 < KX/PBK){
                int k0n = (kt+1)*PBK;
                uint32_t ab = a_u32 + (uint32_t)(((kt+1)&1)*256*PAST)*4u;
                uint32_t bb = b_u32 + (uint32_t)(((kt+1)&1)*32*PBST)*4u;
                #pragma unroll
                for (int i = 0; i < 4; i++){
                    int s = tid + i*512;
                    int r = s >> 3, c4 = (s & 7) * 4;
                    CPA16(ab + (uint32_t)(r*PAST + c4)*4u,
                          xrow + (size_t)r*KX + k0n + c4);
                }
                #pragma unroll
                for (int i = 0; i < 2; i++){
                    int s = tid + i*512;
                    int kr = s >> 5, c4 = (s & 31) * 4;
                    CPA16(bb + (uint32_t)(kr*PBST + c4)*4u,
                          g_Wr + (size_t)(k0n+kr)*NG + n0 + c4);
                }
                CPA_COMMIT();
            }
            // compute k-tile kt
            {
                const float* Ab = Abuf + (kt & 1)*256*PAST;
                const float* Bb = Bbuf + (kt & 1)*32*PBST;
                #pragma unroll
                for (int k8 = 0; k8 < PBK; k8 += 8){
                    uint32_t a[2][4];
                    #pragma unroll
                    for (int mt = 0; mt < 2; mt++){
                        const float* ap = Ab + (wm*32 + mt*16 + qr)*PAST + k8 + qc;
                        a[mt][0] = __float_as_uint(ap[0]);
                        a[mt][1] = __float_as_uint(ap[8*PAST]);
                        a[mt][2] = __float_as_uint(ap[4]);
                        a[mt][3] = __float_as_uint(ap[8*PAST + 4]);
                    }
                    #pragma unroll
                    for (int nt = 0; nt < 8; nt++){
                        const float* bp = Bb + (k8 + qc)*PBST + wn*64 + nt*8 + qr;
                        uint32_t b0 = __float_as_uint(bp[0]);
                        uint32_t b1 = __float_as_uint(bp[4*PBST]);
                        #pragma unroll
                        for (int mt = 0; mt < 2; mt++)
                            mma_tf32(acc[mt][nt], a[mt][0], a[mt][1], a[mt][2],
                                     a[mt][3], b0, b1);
                    }
                }
            }
        }

        // epilogue: write tile to g_Zpre
        const size_t r0 = (size_t)t*Bn;
        #pragma unroll
        for (int mt=0;mt<2;mt++){
            int row = wm*32 + mt*16 + qr;
            #pragma unroll
            for (int nt=0;nt<8;nt++){
                int col = n0 + wn*64 + nt*8 + qc*2;
                float bv0 = bias[col], bv1 = bias[col+1];
                float* z0 = g_Zpre + (r0 + row) * NG + col;
                z0[0] = acc[mt][nt][0] + bv0;
                z0[1] = acc[mt][nt][1] + bv1;
                float* z1 = g_Zpre + (r0 + row + 8) * NG + col;
                z1[0] = acc[mt][nt][2] + bv0;
                z1[1] = acc[mt][nt][3] + bv1;
            }
        }
        __syncthreads();
        if (tid == 0) red_rel_add(&g_zdone[t], 1u);
    }
}

__global__ __launch_bounds__(512) void k_fused(const float* __restrict__ bias,
                                               const float* __restrict__ U,
                                               const float* __restrict__ c0,
                                               float* __restrict__ out){
    extern __shared__ float sm[];
    if (blockIdx.x < NREC)
        consumer_role(U, c0, out, sm);
    else
        producer_role(bias, sm);
}

// ===========================================================================
// k_out (unchanged)
// ===========================================================================
__device__ __forceinline__ void compute_ktile(const float* As, const float* Bs,
                                              float acc[2][4][4], int wm, int wn, int lane){
    const int qr = lane >> 2, qc = lane & 3;
    #pragma unroll
    for (int k8 = 0; k8 < BK; k8 += 8){
        uint32_t a[2][4];
        #pragma unroll
        for (int mm = 0; mm < 2; mm++){
            const float* ap = As + (wm*32 + mm*16 + qr) * ASTR + k8 + qc;
            a[mm][0] = __float_as_uint(ap[0]);
            a[mm][1] = __float_as_uint(ap[8*ASTR]);
            a[mm][2] = __float_as_uint(ap[4]);
            a[mm][3] = __float_as_uint(ap[8*ASTR + 4]);
        }
        #pragma unroll
        for (int nn = 0; nn < 4; nn++){
            const float* bp = Bs + (k8 + qc) * BSTR + wn*32 + nn*8 + qr;
            uint32_t b0 = __float_as_uint(bp[0]);
            uint32_t b1 = __float_as_uint(bp[4*BSTR]);
            #pragma unroll
            for (int mm = 0; mm < 2; mm++)
                mma_tf32(acc[mm][nn], a[mm][0], a[mm][1], a[mm][2], a[mm][3], b0, b1);
        }
    }
}

__global__ __launch_bounds__(256) void k_out(const float* __restrict__ Wo,
                                             const float* __restrict__ bo,
                                             float* __restrict__ out){
    __shared__ float As[BM*ASTR];
    __shared__ float Bs[BK*BSTR];
    const int tid = threadIdx.x, lane = tid & 31, wid = tid >> 5;
    const int wm = wid & 3, wn = wid >> 2;
    const int f0 = blockIdx.x * BN;
    const int r0 = blockIdx.y * BM;

    float acc[2][4][4];
    #pragma unroll
    for (int mm=0;mm<2;mm++)
        #pragma unroll
        for (int nn=0;nn<4;nn++)
            #pragma unroll
            for (int i=0;i<4;i++) acc[mm][nn][i]=0.f;

    for (int kt = 0; kt < DUn/BK; kt++){
        int k0 = kt * BK;
        #pragma unroll
        for (int i = 0; i < 4; i++){
            int idx = tid + i*256;
            int row = idx >> 3, c4 = (idx & 7) * 4;
            float4 v = *reinterpret_cast<const float4*>(
                            g_H + (size_t)(r0+row)*DUn + k0 + c4);
            st4_tf(As + row*ASTR + c4, v);
        }
        #pragma unroll
        for (int i = 0; i < 2; i++){
            int idx = tid + i*256;
            int kr = idx >> 4, c4 = (idx & 15) * 4;
            float4 v = *reinterpret_cast<const float4*>(
                            Wo + (size_t)(k0+kr)*Fn + f0 + c4);
            st4_tf(Bs + kr*BSTR + c4, v);
        }
        __syncthreads();
        compute_ktile(As, Bs, acc, wm, wn, lane);
        __syncthreads();
    }

    const int qr = lane >> 2, qc = lane & 3;
    #pragma unroll
    for (int mm=0;mm<2;mm++){
        int r = r0 + wm*32 + mm*16 + qr;
        #pragma unroll
        for (int nn=0;nn<4;nn++){
            int f = f0 + wn*32 + nn*8 + qc*2;
            float bv0 = bo[f], bv1 = bo[f+1];
            {
                int b = r & (Bn-1), tt = r >> 8;
                float* o = out + ((size_t)b*Tn + tt)*Fn + f;
                o[0] = sigm(acc[mm][nn][0] + bv0);
                o[1] = sigm(acc[mm][nn][1] + bv1);
            }
            {
                int r2 = r + 8;
                int b = r2 & (Bn-1), tt = r2 >> 8;
                float* o = out + ((size_t)b*Tn + tt)*Fn + f;
                o[0] = sigm(acc[mm][nn][2] + bv0);
                o[1] = sigm(acc[mm][nn][3] + bv1);
            }
        }
    }
}

// ===========================================================================
// Prep kernels: tf32-round inputs into global scratch
// ===========================================================================
__global__ void k_prepW(const float* __restrict__ W){
    int idx = blockIdx.x * blockDim.x + threadIdx.x;   // 0 .. 640*512-1 (float4)
    int k = idx >> 9, c4 = (idx & 511) * 4;
    float4 v = *reinterpret_cast<const float4*>(W + (size_t)k*NG + c4);
    st4_tf(g_Wr + (size_t)k*NG + c4, v);
}

__global__ void k_prepX(const float* __restrict__ teacher,
                        const float* __restrict__ cond){
    int idx = blockIdx.x * blockDim.x + threadIdx.x;   // 0 .. Rn*160-1 (float4)
    int r = idx / 160, seg = idx - r*160;
    int c4 = seg * 4;
    int t = r >> 8, b = r & (Bn-1);
    float4 v;
    if (c4 < Fn){
        if (t == 0) v = make_float4(0.f,0.f,0.f,0.f);
        else v = *reinterpret_cast<const float4*>(
                     teacher + ((size_t)b*Tn + (t-1))*Fn + c4);
    } else {
        v = *reinterpret_cast<const float4*>(
                     cond + ((size_t)b*Tn + t)*CUn + (c4 - Fn));
    }
    st4_tf(g_Xr + (size_t)r*KX + c4, v);
}

__global__ void k_init(const float* __restrict__ h0){
    int i = blockIdx.x * blockDim.x + threadIdx.x;
    if (i == 0){ g_work = 0u; g_rbar[0] = 0u; g_rbar[1] = 0u; }
    if (i < Tn) g_zdone[i] = 0u;
    g_h0r[i] = tf2f(f2tf(h0[i]));
}

extern "C" void kernel_launch(void* const* d_in, const int* in_sizes, int n_in,
                              void* d_out, int out_size){
    (void)in_sizes; (void)n_in; (void)out_size;
    const float* conductor = (const float*)d_in[0];
    const float* teacher   = (const float*)d_in[1];
    const float* h0   = (const float*)d_in[2];
    const float* c0   = (const float*)d_in[3];
    const float* W    = (const float*)d_in[4];
    const float* U    = (const float*)d_in[5];
    const float* bias = (const float*)d_in[6];
    const float* Wo   = (const float*)d_in[7];
    const float* bo   = (const float*)d_in[8];
    float* out = (float*)d_out;

    cudaFuncSetAttribute(k_fused, cudaFuncAttributeMaxDynamicSharedMemorySize,
                         SM_FLOATS * (int)sizeof(float));

    k_init<<<(Bn*DUn)/256, 256>>>(h0);
    k_prepW<<<(KX*512)/256, 256>>>(W);
    k_prepX<<<(Rn*160)/256, 256>>>(teacher, conductor);
    k_fused<<<NCTA_ALL, 512, SM_FLOATS * sizeof(float)>>>(bias, U, c0, out);
    k_out<<<dim3(Fn/BN, Rn/BM), 256>>>(Wo, bo, out);
}

// round 17
// speedup vs baseline: 1.0388x; 1.0388x over previous
#include <cuda_runtime.h>
#include <cstdint>
#include <math.h>

// Problem dims
#define Bn  256
#define Tn  512
#define Fn  128
#define CUn 512
#define DUn 512
#define KX  640
#define NG  2048
#define Rn  (Bn*Tn)

// Producer v2 tiling (round-14 verified): CTA tile 256 x 64, double-buffered
#define PBK  32
#define PAST 36
#define PBST 72
#define PA_OFF 0                         // 2 x 256*36 = 18432 floats
#define PB_OFF (2*256*PAST)              // 2 x 32*72  =  4608 floats
#define ZTILES_T 32                      // Zpre tiles per t (2048/64)
#define TOTAL_TILES (Tn * ZTILES_T)

// k_out tiling
#define BM 128
#define BN 64
#define BK 32
#define ASTR 36
#define BSTR 72

// Consumer config: 64 CTAs = 2 row-groups x 32 col-groups
#define NREC   64
#define NCTA_ALL 148
#define NRGC   32
#define UST    72        // 72%32==8; 72*4 % 16 == 0 (LDS.128 aligned)
#define BKC    64
#define H64S   68
#define NKT    (DUn/BKC)

// Scratch
__device__ float g_Zpre[(size_t)Rn * NG];
__device__ float g_H[(size_t)Rn * DUn];
__device__ float g_h0r[Bn * DUn];
__device__ float g_Wr[(size_t)KX * NG];      // tf32-rounded W
__device__ float g_Xr[(size_t)Rn * KX];      // tf32-rounded [teacher_{t-1} | cond_t]
__device__ unsigned g_rbar[2];
__device__ unsigned g_work;
__device__ unsigned g_zdone[Tn];

__device__ __forceinline__ uint32_t f2tf(float x){
    uint32_t r; asm("cvt.rna.tf32.f32 %0, %1;" : "=r"(r) : "f"(x)); return r;
}
__device__ __forceinline__ float tf2f(uint32_t u){ return __uint_as_float(u); }
__device__ __forceinline__ void st4_tf(float* dst, float4 v){
    dst[0]=tf2f(f2tf(v.x)); dst[1]=tf2f(f2tf(v.y));
    dst[2]=tf2f(f2tf(v.z)); dst[3]=tf2f(f2tf(v.w));
}
__device__ __forceinline__ void mma_tf32(float d[4],
        uint32_t a0, uint32_t a1, uint32_t a2, uint32_t a3,
        uint32_t b0, uint32_t b1){
    asm volatile(
        "mma.sync.aligned.m16n8k8.row.col.f32.tf32.tf32.f32 "
        "{%0,%1,%2,%3}, {%4,%5,%6,%7}, {%8,%9}, {%0,%1,%2,%3};\n"
        : "+f"(d[0]), "+f"(d[1]), "+f"(d[2]), "+f"(d[3])
        : "r"(a0), "r"(a1), "r"(a2), "r"(a3), "r"(b0), "r"(b1));
}
__device__ __forceinline__ float sigm(float x){ return 1.f/(1.f + __expf(-x)); }

__device__ __forceinline__ unsigned ld_acq(const unsigned* p){
    unsigned v;
    asm volatile("ld.global.acquire.gpu.b32 %0, [%1];" : "=r"(v) : "l"(p));
    return v;
}
__device__ __forceinline__ void red_rel_add(unsigned* p, unsigned v){
    asm volatile("red.release.gpu.global.add.u32 [%0], %1;" :: "l"(p), "r"(v) : "memory");
}
__device__ __forceinline__ void nsleep(unsigned ns){
    asm volatile("nanosleep.u32 %0;" :: "r"(ns));
}

#define CPA16(dst_u32, src_ptr) \
    asm volatile("cp.async.ca.shared.global [%0], [%1], 16;\n" \
                 :: "r"(dst_u32), "l"(src_ptr))
#define CPA_COMMIT() asm volatile("cp.async.commit_group;\n" ::: "memory")

// Consumer SMEM floats: Us 512*72 = 36864 | A ring 2 x 128*68 = 17408
#define US_OFF   0
#define AS_OFF   (512*UST)
#define SM_FLOATS (AS_OFF + 2*128*H64S)      // 54272 floats = 217088 B

// ===========================================================================
// Consumer: CTA (rg,cg) = rows rg*128..+128, units cg*16..+16.
// 16 warps = 8M x 2N, warp 16x32, serial K, c in registers.
// NEW: U slice stored UNIT-MAJOR (c = unit*4 + gate) so each thread's four
// gate B-values are contiguous -> 2x LDS.128 per k8 instead of 8x LDS.32.
// Same values, same accumulation order -> bit-identical numerics.
// ===========================================================================
__device__ void consumer_role(const float* __restrict__ U,
                              const float* __restrict__ c0,
                              float* __restrict__ out,
                              float* sm){
    float* Us = sm + US_OFF;
    float* As = sm + AS_OFF;

    const int tid = threadIdx.x, lane = tid & 31, wid = tid >> 5;
    const int qr = lane >> 2, qc = lane & 3;
    const int wm = wid >> 1, wn = wid & 1;
    const int rg = blockIdx.x >> 5, cg = blockIdx.x & 31;
    const int mrow = wm * 16;
    const int j0 = cg * 16;
    const int ju = j0 + wn*8 + qc*2;
    const int ub = (wn*8 + qr) * 4;            // this thread's B float4 offset

    // one-time: U slice (tf32) into SMEM, UNIT-MAJOR: Us[k][u*4+q]
    for (int i = tid; i < 512*64; i += 512){
        int k = i >> 6, c = i & 63;
        int u = c >> 2, q = c & 3;
        Us[k*UST + c] = tf2f(f2tf(U[(size_t)k*NG + q*DUn + j0 + u]));
    }
    float creg[2][2];
    {
        int grow = rg*128 + mrow + qr;
        float2 cA = *reinterpret_cast<const float2*>(c0 + (size_t)grow*DUn + ju);
        float2 cB = *reinterpret_cast<const float2*>(c0 + (size_t)(grow+8)*DUn + ju);
        creg[0][0]=cA.x; creg[0][1]=cA.y; creg[1][0]=cB.x; creg[1][1]=cB.y;
    }
    __syncthreads();

    const uint32_t as_u32 = (uint32_t)__cvta_generic_to_shared(As);

    for (int t = 0; t < Tn; t++){
        const float* hsrc = ((t == 0) ? g_h0r : (g_H + (size_t)(t-1)*Bn*DUn))
                            + (size_t)rg*128*DUn;

        if (tid == 0){
            unsigned s = 0;
            while (ld_acq(&g_zdone[t]) < (unsigned)ZTILES_T){
                nsleep(s); if (s < 256) s += 64;
            }
        }
        __syncthreads();

        float2 zp[2][4];
        {
            const float* zr0 = g_Zpre + ((size_t)t*Bn + rg*128 + mrow + qr)*NG + ju;
            const float* zr1 = zr0 + 8*NG;
            #pragma unroll
            for (int g = 0; g < 4; g++){
                zp[0][g] = *reinterpret_cast<const float2*>(zr0 + g*DUn);
                zp[1][g] = *reinterpret_cast<const float2*>(zr1 + g*DUn);
            }
        }

        #pragma unroll
        for (int i = 0; i < 4; i++){
            int s = tid + i*512;
            int r = s >> 4, c4 = (s & 15) * 4;
            CPA16(as_u32 + (uint32_t)(r*H64S + c4)*4u, hsrc + (size_t)r*DUn + c4);
        }
        CPA_COMMIT();

        float acc[4][4];
        #pragma unroll
        for (int nt=0;nt<4;nt++)
            #pragma unroll
            for (int i=0;i<4;i++) acc[nt][i]=0.f;

        for (int kt = 0; kt < NKT; kt++){
            asm volatile("cp.async.wait_group 0;\n" ::: "memory");
            __syncthreads();
            if (kt + 1 < NKT){
                uint32_t bb = as_u32 + (uint32_t)(((kt+1)&1)*128*H64S)*4u;
                int k0n = (kt+1)*BKC;
                #pragma unroll
                for (int i = 0; i < 4; i++){
                    int s = tid + i*512;
                    int r = s >> 4, c4 = (s & 15) * 4;
                    CPA16(bb + (uint32_t)(r*H64S + c4)*4u,
                          hsrc + (size_t)r*DUn + k0n + c4);
                }
                CPA_COMMIT();
            }
            {
                const float* Asb = As + (kt & 1)*128*H64S;
                const int k0 = kt * BKC;
                #pragma unroll
                for (int k8 = 0; k8 < BKC; k8 += 8){
                    const float* ap = Asb + (mrow + qr) * H64S + k8 + qc;
                    uint32_t a0 = __float_as_uint(ap[0]);
                    uint32_t a1 = __float_as_uint(ap[8*H64S]);
                    uint32_t a2 = __float_as_uint(ap[4]);
                    uint32_t a3 = __float_as_uint(ap[8*H64S + 4]);
                    const float* bp = Us + (k0 + k8 + qc)*UST + ub;
                    float4 bv0 = *reinterpret_cast<const float4*>(bp);
                    float4 bv1 = *reinterpret_cast<const float4*>(bp + 4*UST);
                    mma_tf32(acc[0], a0, a1, a2, a3,
                             __float_as_uint(bv0.x), __float_as_uint(bv1.x));
                    mma_tf32(acc[1], a0, a1, a2, a3,
                             __float_as_uint(bv0.y), __float_as_uint(bv1.y));
                    mma_tf32(acc[2], a0, a1, a2, a3,
                             __float_as_uint(bv0.z), __float_as_uint(bv1.z));
                    mma_tf32(acc[3], a0, a1, a2, a3,
                             __float_as_uint(bv0.w), __float_as_uint(bv1.w));
                }
            }
        }

        {
            float hv[2][2], cvv[2][2];
            #pragma unroll
            for (int rr = 0; rr < 2; rr++){
                #pragma unroll
                for (int uu = 0; uu < 2; uu++){
                    int k = rr*2 + uu;
                    float zi = acc[0][k] + (uu ? zp[rr][0].y : zp[rr][0].x);
                    float zf = acc[1][k] + (uu ? zp[rr][1].y : zp[rr][1].x);
                    float zg = acc[2][k] + (uu ? zp[rr][2].y : zp[rr][2].x);
                    float zo = acc[3][k] + (uu ? zp[rr][3].y : zp[rr][3].x);
                    float si = sigm(zi), sf = sigm(zf), so = sigm(zo);
                    float tg = tanhf(zg);
                    float cn = sf*creg[rr][uu] + si*tg;
                    float hn = so * tanhf(cn);
                    creg[rr][uu] = cn;
                    cvv[rr][uu] = cn;
                    hv[rr][uu] = tf2f(f2tf(hn));
                }
            }
            #pragma unroll
            for (int rr = 0; rr < 2; rr++){
                int grow = rg*128 + mrow + qr + rr*8;
                *reinterpret_cast<float2*>(g_H + ((size_t)t*Bn + grow)*DUn + ju)
                    = make_float2(hv[rr][0], hv[rr][1]);
                if (t == Tn - 1){
                    *reinterpret_cast<float2*>(out + (size_t)Bn*Tn*Fn
                                               + (size_t)grow*DUn + ju)
                        = make_float2(hv[rr][0], hv[rr][1]);
                    *reinterpret_cast<float2*>(out + (size_t)Bn*Tn*Fn + Bn*DUn
                                               + (size_t)grow*DUn + ju)
                        = make_float2(cvv[rr][0], cvv[rr][1]);
                }
            }
        }
        __syncthreads();

        if (t < Tn - 1){
            if (tid == 0){
                red_rel_add(&g_rbar[rg], 1u);
                unsigned target = (unsigned)NRGC * (unsigned)(t + 1);
                unsigned s = 0;
                while (ld_acq(&g_rbar[rg]) < target){ nsleep(s); if (s < 128) s += 32; }
            }
            __syncthreads();
        }
    }
}

// ===========================================================================
// Producer v2 (round-14 verified): Zpre tiles 256x64, t-major queue,
// warp tile 32x32 (2m16 x 4n8), double-buffered cp.async, one sync/k-tile.
// ===========================================================================
__device__ void producer_role(const float* __restrict__ bias, float* sm){
    float* Abuf = sm + PA_OFF;
    float* Bbuf = sm + PB_OFF;
    __shared__ unsigned s_tile;
    const int tid = threadIdx.x, lane = tid & 31, wid = tid >> 5;
    const int wm = wid >> 1, wn = wid & 1;
    const int qr = lane >> 2, qc = lane & 3;

    const uint32_t a_u32 = (uint32_t)__cvta_generic_to_shared(Abuf);
    const uint32_t b_u32 = (uint32_t)__cvta_generic_to_shared(Bbuf);

    for (;;){
        if (tid == 0) s_tile = atomicAdd(&g_work, 1u);
        __syncthreads();
        unsigned n = s_tile;
        if (n >= (unsigned)TOTAL_TILES) break;
        __syncthreads();
        const int t  = (int)(n >> 5);
        const int n0 = (int)(n & 31) * 64;
        const float* xrow = g_Xr + (size_t)t*Bn*KX;

        float acc[2][4][4];
        #pragma unroll
        for (int mt=0;mt<2;mt++)
            #pragma unroll
            for (int nt=0;nt<4;nt++)
                #pragma unroll
                for (int i=0;i<4;i++) acc[mt][nt][i]=0.f;

        #pragma unroll
        for (int i = 0; i < 4; i++){
            int s = tid + i*512;
            int r = s >> 3, c4 = (s & 7) * 4;
            CPA16(a_u32 + (uint32_t)(r*PAST + c4)*4u, xrow + (size_t)r*KX + c4);
        }
        {
            int kr = tid >> 4, c4 = (tid & 15) * 4;
            CPA16(b_u32 + (uint32_t)(kr*PBST + c4)*4u,
                  g_Wr + (size_t)kr*NG + n0 + c4);
        }
        CPA_COMMIT();

        for (int kt = 0; kt < KX/PBK; kt++){
            asm volatile("cp.async.wait_group 0;\n" ::: "memory");
            __syncthreads();
            if (kt + 1 < KX/PBK){
                int k0n = (kt+1)*PBK;
                uint32_t ab = a_u32 + (uint32_t)(((kt+1)&1)*256*PAST)*4u;
                uint32_t bb = b_u32 + (uint32_t)(((kt+1)&1)*32*PBST)*4u;
                #pragma unroll
                for (int i = 0; i < 4; i++){
                    int s = tid + i*512;
                    int r = s >> 3, c4 = (s & 7) * 4;
                    CPA16(ab + (uint32_t)(r*PAST + c4)*4u,
                          xrow + (size_t)r*KX + k0n + c4);
                }
                {
                    int kr = tid >> 4, c4 = (tid & 15) * 4;
                    CPA16(bb + (uint32_t)(kr*PBST + c4)*4u,
                          g_Wr + (size_t)(k0n+kr)*NG + n0 + c4);
                }
                CPA_COMMIT();
            }
            {
                const float* Ab = Abuf + (kt & 1)*256*PAST;
                const float* Bb = Bbuf + (kt & 1)*32*PBST;
                #pragma unroll
                for (int k8 = 0; k8 < PBK; k8 += 8){
                    uint32_t a[2][4];
                    #pragma unroll
                    for (int mt = 0; mt < 2; mt++){
                        const float* ap = Ab + (wm*32 + mt*16 + qr)*PAST + k8 + qc;
                        a[mt][0] = __float_as_uint(ap[0]);
                        a[mt][1] = __float_as_uint(ap[8*PAST]);
                        a[mt][2] = __float_as_uint(ap[4]);
                        a[mt][3] = __float_as_uint(ap[8*PAST + 4]);
                    }
                    #pragma unroll
                    for (int nt = 0; nt < 4; nt++){
                        const float* bp = Bb + (k8 + qc)*PBST + wn*32 + nt*8 + qr;
                        uint32_t b0 = __float_as_uint(bp[0]);
                        uint32_t b1 = __float_as_uint(bp[4*PBST]);
                        #pragma unroll
                        for (int mt = 0; mt < 2; mt++)
                            mma_tf32(acc[mt][nt], a[mt][0], a[mt][1], a[mt][2],
                                     a[mt][3], b0, b1);
                    }
                }
            }
        }

        const size_t r0 = (size_t)t*Bn;
        #pragma unroll
        for (int mt=0;mt<2;mt++){
            int row = wm*32 + mt*16 + qr;
            #pragma unroll
            for (int nt=0;nt<4;nt++){
                int col = n0 + wn*32 + nt*8 + qc*2;
                float bv0 = bias[col], bv1 = bias[col+1];
                float* z0 = g_Zpre + (r0 + row) * NG + col;
                z0[0] = acc[mt][nt][0] + bv0;
                z0[1] = acc[mt][nt][1] + bv1;
                float* z1 = g_Zpre + (r0 + row + 8) * NG + col;
                z1[0] = acc[mt][nt][2] + bv0;
                z1[1] = acc[mt][nt][3] + bv1;
            }
        }
        __syncthreads();
        if (tid == 0) red_rel_add(&g_zdone[t], 1u);
    }
}

__global__ __launch_bounds__(512) void k_fused(const float* __restrict__ bias,
                                               const float* __restrict__ U,
                                               const float* __restrict__ c0,
                                               float* __restrict__ out){
    extern __shared__ float sm[];
    if (blockIdx.x < NREC)
        consumer_role(U, c0, out, sm);
    else
        producer_role(bias, sm);
}

// ===========================================================================
// k_out (unchanged)
// ===========================================================================
__device__ __forceinline__ void compute_ktile(const float* As, const float* Bs,
                                              float acc[2][4][4], int wm, int wn, int lane){
    const int qr = lane >> 2, qc = lane & 3;
    #pragma unroll
    for (int k8 = 0; k8 < BK; k8 += 8){
        uint32_t a[2][4];
        #pragma unroll
        for (int mm = 0; mm < 2; mm++){
            const float* ap = As + (wm*32 + mm*16 + qr) * ASTR + k8 + qc;
            a[mm][0] = __float_as_uint(ap[0]);
            a[mm][1] = __float_as_uint(ap[8*ASTR]);
            a[mm][2] = __float_as_uint(ap[4]);
            a[mm][3] = __float_as_uint(ap[8*ASTR + 4]);
        }
        #pragma unroll
        for (int nn = 0; nn < 4; nn++){
            const float* bp = Bs + (k8 + qc) * BSTR + wn*32 + nn*8 + qr;
            uint32_t b0 = __float_as_uint(bp[0]);
            uint32_t b1 = __float_as_uint(bp[4*BSTR]);
            #pragma unroll
            for (int mm = 0; mm < 2; mm++)
                mma_tf32(acc[mm][nn], a[mm][0], a[mm][1], a[mm][2], a[mm][3], b0, b1);
        }
    }
}

__global__ __launch_bounds__(256) void k_out(const float* __restrict__ Wo,
                                             const float* __restrict__ bo,
                                             float* __restrict__ out){
    __shared__ float As[BM*ASTR];
    __shared__ float Bs[BK*BSTR];
    const int tid = threadIdx.x, lane = tid & 31, wid = tid >> 5;
    const int wm = wid & 3, wn = wid >> 2;
    const int f0 = blockIdx.x * BN;
    const int r0 = blockIdx.y * BM;

    float acc[2][4][4];
    #pragma unroll
    for (int mm=0;mm<2;mm++)
        #pragma unroll
        for (int nn=0;nn<4;nn++)
            #pragma unroll
            for (int i=0;i<4;i++) acc[mm][nn][i]=0.f;

    for (int kt = 0; kt < DUn/BK; kt++){
        int k0 = kt * BK;
        #pragma unroll
        for (int i = 0; i < 4; i++){
            int idx = tid + i*256;
            int row = idx >> 3, c4 = (idx & 7) * 4;
            float4 v = *reinterpret_cast<const float4*>(
                            g_H + (size_t)(r0+row)*DUn + k0 + c4);
            st4_tf(As + row*ASTR + c4, v);
        }
        #pragma unroll
        for (int i = 0; i < 2; i++){
            int idx = tid + i*256;
            int kr = idx >> 4, c4 = (idx & 15) * 4;
            float4 v = *reinterpret_cast<const float4*>(
                            Wo + (size_t)(k0+kr)*Fn + f0 + c4);
            st4_tf(Bs + kr*BSTR + c4, v);
        }
        __syncthreads();
        compute_ktile(As, Bs, acc, wm, wn, lane);
        __syncthreads();
    }

    const int qr = lane >> 2, qc = lane & 3;
    #pragma unroll
    for (int mm=0;mm<2;mm++){
        int r = r0 + wm*32 + mm*16 + qr;
        #pragma unroll
        for (int nn=0;nn<4;nn++){
            int f = f0 + wn*32 + nn*8 + qc*2;
            float bv0 = bo[f], bv1 = bo[f+1];
            {
                int b = r & (Bn-1), tt = r >> 8;
                float* o = out + ((size_t)b*Tn + tt)*Fn + f;
                o[0] = sigm(acc[mm][nn][0] + bv0);
                o[1] = sigm(acc[mm][nn][1] + bv1);
            }
            {
                int r2 = r + 8;
                int b = r2 & (Bn-1), tt = r2 >> 8;
                float* o = out + ((size_t)b*Tn + tt)*Fn + f;
                o[0] = sigm(acc[mm][nn][2] + bv0);
                o[1] = sigm(acc[mm][nn][3] + bv1);
            }
        }
    }
}

// ===========================================================================
// Prep kernels
// ===========================================================================
__global__ void k_prepW(const float* __restrict__ W){
    int idx = blockIdx.x * blockDim.x + threadIdx.x;
    int k = idx >> 9, c4 = (idx & 511) * 4;
    float4 v = *reinterpret_cast<const float4*>(W + (size_t)k*NG + c4);
    st4_tf(g_Wr + (size_t)k*NG + c4, v);
}

__global__ void k_prepX(const float* __restrict__ teacher,
                        const float* __restrict__ cond){
    int idx = blockIdx.x * blockDim.x + threadIdx.x;
    int r = idx / 160, seg = idx - r*160;
    int c4 = seg * 4;
    int t = r >> 8, b = r & (Bn-1);
    float4 v;
    if (c4 < Fn){
        if (t == 0) v = make_float4(0.f,0.f,0.f,0.f);
        else v = *reinterpret_cast<const float4*>(
                     teacher + ((size_t)b*Tn + (t-1))*Fn + c4);
    } else {
        v = *reinterpret_cast<const float4*>(
                     cond + ((size_t)b*Tn + t)*CUn + (c4 - Fn));
    }
    st4_tf(g_Xr + (size_t)r*KX + c4, v);
}

__global__ void k_init(const float* __restrict__ h0){
    int i = blockIdx.x * blockDim.x + threadIdx.x;
    if (i == 0){ g_work = 0u; g_rbar[0] = 0u; g_rbar[1] = 0u; }
    if (i < Tn) g_zdone[i] = 0u;
    g_h0r[i] = tf2f(f2tf(h0[i]));
}

extern "C" void kernel_launch(void* const* d_in, const int* in_sizes, int n_in,
                              void* d_out, int out_size){
    (void)in_sizes; (void)n_in; (void)out_size;
    const float* conductor = (const float*)d_in[0];
    const float* teacher   = (const float*)d_in[1];
    const float* h0   = (const float*)d_in[2];
    const float* c0   = (const float*)d_in[3];
    const float* W    = (const float*)d_in[4];
    const float* U    = (const float*)d_in[5];
    const float* bias = (const float*)d_in[6];
    const float* Wo   = (const float*)d_in[7];
    const float* bo   = (const float*)d_in[8];
    float* out = (float*)d_out;

    cudaFuncSetAttribute(k_fused, cudaFuncAttributeMaxDynamicSharedMemorySize,
                         SM_FLOATS * (int)sizeof(float));

    k_init<<<(Bn*DUn)/256, 256>>>(h0);
    k_prepW<<<(KX*512)/256, 256>>>(W);
    k_prepX<<<(Rn*160)/256, 256>>>(teacher, conductor);
    k_fused<<<NCTA_ALL, 512, SM_FLOATS * sizeof(float)>>>(bias, U, c0, out);
    k_out<<<dim3(Fn/BN, Rn/BM), 256>>>(Wo, bo, out);
}